// round 1
// baseline (speedup 1.0000x reference)
#include <cuda_runtime.h>
#include <cstddef>

// ---------------------------------------------------------------------------
// Problem constants
// ---------------------------------------------------------------------------
#define BSZ   4096
#define NALLY 31
#define NEN   32
#define D_OWN 128
#define D_AL  64
#define D_EN  65
#define ADIM  128
#define EDIM  256
#define HDIM  512
#define NACT  6
#define QOUT  (NACT + NEN)   // 38
#define M_AQ  (NEN * BSZ)    // 131072

// ---------------------------------------------------------------------------
// Scratch (static device globals; no runtime allocation)
// ---------------------------------------------------------------------------
__device__ float g_query [BSZ * ADIM];
__device__ float g_qa    [BSZ * D_AL];
__device__ float g_qe    [BSZ * D_EN];
__device__ float g_afw   [BSZ * D_AL];
__device__ float g_efw   [BSZ * D_EN];
__device__ float g_tot   [BSZ * 3 * EDIM];          // [B,768]
__device__ float g_gi    [BSZ * 3 * HDIM];
__device__ float g_gh    [BSZ * 3 * HDIM];
__device__ float g_hterm [BSZ * HDIM];
__device__ float g_M     [HDIM * HDIM];
__device__ float g_cvec  [HDIM];
__device__ float g_wihT  [768 * 1536];
__device__ float g_whhT  [512 * 1536];
__device__ float g_WakT  [ADIM * D_AL];
__device__ float g_WekT  [ADIM * D_EN];
__device__ float g_relu1 [(size_t)M_AQ * HDIM];     // 268 MB
__device__ float g_aqpart[4 * M_AQ];

// ---------------------------------------------------------------------------
// Generic SGEMM: C[M,N] = A[M,K] @ B[K,N] (+bias) (+relu)
// 128x128 tile, BK=8, 256 threads, 8x8 per-thread microtile.
// ---------------------------------------------------------------------------
__global__ void sgemm_kernel(const float* __restrict__ A, const float* __restrict__ Bm,
                             const float* __restrict__ bias, float* __restrict__ C,
                             int M, int N, int K, int lda, int ldb, int ldc, int relu)
{
    constexpr int BM = 128, BN = 128, BK = 8, TM = 8, TN = 8;
    __shared__ float As[BK][BM];
    __shared__ float Bs[BK][BN];

    const int tid = threadIdx.x;
    const int tx = tid & 15, ty = tid >> 4;
    const int rowBase = blockIdx.y * BM;
    const int colBase = blockIdx.x * BN;

    float acc[TM][TN];
#pragma unroll
    for (int i = 0; i < TM; i++)
#pragma unroll
        for (int j = 0; j < TN; j++) acc[i][j] = 0.f;

    const int aRow = tid >> 1, aCol = (tid & 1) * 4;
    const int bRow = tid >> 5, bCol = (tid & 31) * 4;

    for (int k0 = 0; k0 < K; k0 += BK) {
#pragma unroll
        for (int i = 0; i < 4; i++) {
            int k = k0 + aCol + i;
            int m = rowBase + aRow;
            As[aCol + i][aRow] = (m < M && k < K) ? __ldg(&A[(size_t)m * lda + k]) : 0.f;
        }
#pragma unroll
        for (int i = 0; i < 4; i++) {
            int k = k0 + bRow;
            int n = colBase + bCol + i;
            Bs[bRow][bCol + i] = (k < K && n < N) ? __ldg(&Bm[(size_t)k * ldb + n]) : 0.f;
        }
        __syncthreads();
#pragma unroll
        for (int kk = 0; kk < BK; kk++) {
            float a[TM], b[TN];
#pragma unroll
            for (int i = 0; i < TM; i++) a[i] = As[kk][ty * TM + i];
#pragma unroll
            for (int j = 0; j < TN; j++) b[j] = Bs[kk][tx * TN + j];
#pragma unroll
            for (int i = 0; i < TM; i++)
#pragma unroll
                for (int j = 0; j < TN; j++) acc[i][j] += a[i] * b[j];
        }
        __syncthreads();
    }

#pragma unroll
    for (int i = 0; i < TM; i++) {
        int r = rowBase + ty * TM + i;
        if (r >= M) continue;
#pragma unroll
        for (int j = 0; j < TN; j++) {
            int c = colBase + tx * TN + j;
            if (c >= N) continue;
            float v = acc[i][j];
            if (bias) v += __ldg(&bias[c]);
            if (relu) v = fmaxf(v, 0.f);
            C[(size_t)r * ldc + c] = v;
        }
    }
}

// ---------------------------------------------------------------------------
// Fused aq GEMM: inner = relu1[M_AQ,512] @ M[512,512]; per element
// v = relu(inner + hterm[row%B, col]); partial[row] += v * Wa2[col]
// Writes column-block partial sums (gridDim.x = 4) -> g_aqpart.
// ---------------------------------------------------------------------------
__global__ void sgemm_aq_kernel(const float* __restrict__ A, const float* __restrict__ Bm,
                                const float* __restrict__ hterm, const float* __restrict__ Wa2,
                                float* __restrict__ aqpart)
{
    constexpr int BM = 128, BN = 128, BK = 8, TM = 8, TN = 8, K = HDIM;
    __shared__ float As[BK][BM];
    __shared__ float Bs[BK][BN];
    __shared__ float Red[BM][17];

    const int tid = threadIdx.x;
    const int tx = tid & 15, ty = tid >> 4;
    const int rowBase = blockIdx.y * BM;
    const int colBase = blockIdx.x * BN;

    float acc[TM][TN];
#pragma unroll
    for (int i = 0; i < TM; i++)
#pragma unroll
        for (int j = 0; j < TN; j++) acc[i][j] = 0.f;

    const int aRow = tid >> 1, aCol = (tid & 1) * 4;
    const int bRow = tid >> 5, bCol = (tid & 31) * 4;

    for (int k0 = 0; k0 < K; k0 += BK) {
#pragma unroll
        for (int i = 0; i < 4; i++)
            As[aCol + i][aRow] = __ldg(&A[(size_t)(rowBase + aRow) * K + k0 + aCol + i]);
#pragma unroll
        for (int i = 0; i < 4; i++)
            Bs[bRow][bCol + i] = __ldg(&Bm[(size_t)(k0 + bRow) * HDIM + colBase + bCol + i]);
        __syncthreads();
#pragma unroll
        for (int kk = 0; kk < BK; kk++) {
            float a[TM], b[TN];
#pragma unroll
            for (int i = 0; i < TM; i++) a[i] = As[kk][ty * TM + i];
#pragma unroll
            for (int j = 0; j < TN; j++) b[j] = Bs[kk][tx * TN + j];
#pragma unroll
            for (int i = 0; i < TM; i++)
#pragma unroll
                for (int j = 0; j < TN; j++) acc[i][j] += a[i] * b[j];
        }
        __syncthreads();
    }

    float w[TN];
#pragma unroll
    for (int j = 0; j < TN; j++) w[j] = __ldg(&Wa2[colBase + tx * TN + j]);

#pragma unroll
    for (int i = 0; i < TM; i++) {
        int r = rowBase + ty * TM + i;
        int b = r & (BSZ - 1);             // row = n*B + b, B power of two
        float s = 0.f;
#pragma unroll
        for (int j = 0; j < TN; j++) {
            int c = colBase + tx * TN + j;
            float v = acc[i][j] + __ldg(&hterm[(size_t)b * HDIM + c]);
            s += fmaxf(v, 0.f) * w[j];
        }
        Red[ty * TM + i][tx] = s;
    }
    __syncthreads();
    if (tid < BM) {
        float s = 0.f;
#pragma unroll
        for (int t = 0; t < 16; t++) s += Red[tid][t];
        aqpart[(size_t)blockIdx.x * M_AQ + rowBase + tid] = s;
    }
}

// ---------------------------------------------------------------------------
// Attention: one warp per batch element. energy over N agents on D-dim raw
// features dotted with the down-projected query; softmax; output the
// attention-weighted raw-feature vector fw[b, D].
// ---------------------------------------------------------------------------
template <int D, int Nn>
__global__ void attn_kernel(const float* __restrict__ feats,   // [Nn, B, D]
                            const float* __restrict__ qproj,   // [B, D]
                            float* __restrict__ fw)            // [B, D]
{
    constexpr int NC = (D + 31) / 32;
    const int warp = (blockIdx.x * blockDim.x + threadIdx.x) >> 5;
    const int lane = threadIdx.x & 31;
    if (warp >= BSZ) return;
    const int b = warp;

    float qv[NC];
#pragma unroll
    for (int c = 0; c < NC; c++) {
        int d = lane + c * 32;
        qv[c] = (d < D) ? qproj[(size_t)b * D + d] : 0.f;
    }

    const float scale = rsqrtf((float)ADIM);
    float myE = 0.f, m = -1e30f;
    for (int n = 0; n < Nn; n++) {
        const float* f = feats + ((size_t)n * BSZ + b) * D;
        float p = 0.f;
#pragma unroll
        for (int c = 0; c < NC; c++) {
            int d = lane + c * 32;
            if (d < D) p += f[d] * qv[c];
        }
#pragma unroll
        for (int o = 16; o; o >>= 1) p += __shfl_xor_sync(0xffffffffu, p, o);
        p *= scale;
        if (lane == n) myE = p;
        m = fmaxf(m, p);
    }
    float wgt = (lane < Nn) ? expf(myE - m) : 0.f;
    float s = wgt;
#pragma unroll
    for (int o = 16; o; o >>= 1) s += __shfl_xor_sync(0xffffffffu, s, o);
    const float attnW = wgt / s;

    float acc[NC];
#pragma unroll
    for (int c = 0; c < NC; c++) acc[c] = 0.f;
    for (int n = 0; n < Nn; n++) {
        float a = __shfl_sync(0xffffffffu, attnW, n);
        const float* f = feats + ((size_t)n * BSZ + b) * D;
#pragma unroll
        for (int c = 0; c < NC; c++) {
            int d = lane + c * 32;
            if (d < D) acc[c] += a * f[d];
        }
    }
#pragma unroll
    for (int c = 0; c < NC; c++) {
        int d = lane + c * 32;
        if (d < D) fw[(size_t)b * D + d] = acc[c];
    }
}

// ---------------------------------------------------------------------------
// GRU gate fusion: h = (1-z)*n + z*h_prev  (torch r,z,n gate order)
// ---------------------------------------------------------------------------
__global__ void gru_gate_kernel(const float* __restrict__ gi, const float* __restrict__ gh,
                                const float* __restrict__ hprev, float* __restrict__ hout)
{
    int idx = blockIdx.x * blockDim.x + threadIdx.x;
    if (idx >= BSZ * HDIM) return;
    int b = idx >> 9, k = idx & (HDIM - 1);
    const float* gib = gi + (size_t)b * 3 * HDIM;
    const float* ghb = gh + (size_t)b * 3 * HDIM;
    float ir = gib[k], iz = gib[HDIM + k], in_ = gib[2 * HDIM + k];
    float hr = ghb[k], hz = ghb[HDIM + k], hn  = ghb[2 * HDIM + k];
    float r = 1.f / (1.f + expf(-(ir + hr)));
    float z = 1.f / (1.f + expf(-(iz + hz)));
    float n = tanhf(in_ + r * hn);
    hout[idx] = (1.f - z) * n + z * hprev[idx];
}

// wo_q head: out[b, 0:6] = h[b] @ Wwo + bwo
__global__ void woq_kernel(const float* __restrict__ h, const float* __restrict__ Wwo,
                           const float* __restrict__ bwo, float* __restrict__ out)
{
    int idx = blockIdx.x * blockDim.x + threadIdx.x;
    if (idx >= BSZ * NACT) return;
    int b = idx / NACT, j = idx - b * NACT;
    const float* hb = h + (size_t)b * HDIM;
    float s = bwo[j];
#pragma unroll 8
    for (int k = 0; k < HDIM; k++) s += hb[k] * __ldg(&Wwo[k * NACT + j]);
    out[(size_t)b * QOUT + j] = s;
}

// aq finish: sum 4 column-block partials + ba2 -> out[b, 6+n]
__global__ void aqfin_kernel(const float* __restrict__ part, const float* __restrict__ ba2,
                             float* __restrict__ out)
{
    int idx = blockIdx.x * blockDim.x + threadIdx.x;
    if (idx >= M_AQ) return;
    int n = idx >> 12, b = idx & (BSZ - 1);
    float s = ba2[0];
#pragma unroll
    for (int c = 0; c < 4; c++) s += part[(size_t)c * M_AQ + idx];
    out[(size_t)b * QOUT + NACT + n] = s;
}

// cvec[j] = be2 @ Wa1_top[:, j] + ba1[j]   (one warp per j)
__global__ void cvec_kernel(const float* __restrict__ be2, const float* __restrict__ Wa1,
                            const float* __restrict__ ba1, float* __restrict__ cvec)
{
    int warp = (blockIdx.x * blockDim.x + threadIdx.x) >> 5;
    int lane = threadIdx.x & 31;
    if (warp >= HDIM) return;
    float s = 0.f;
    for (int k = lane; k < HDIM; k += 32) s += be2[k] * Wa1[(size_t)k * HDIM + warp];
#pragma unroll
    for (int o = 16; o; o >>= 1) s += __shfl_xor_sync(0xffffffffu, s, o);
    if (lane == 0) cvec[warp] = s + ba1[warp];
}

// naive transpose: out[j, i] = in[i, j]  for in[R, C]
__global__ void transpose_kernel(const float* __restrict__ in, float* __restrict__ out,
                                 int R, int C)
{
    int idx = blockIdx.x * blockDim.x + threadIdx.x;
    if (idx >= R * C) return;
    int i = idx / C, j = idx - i * C;
    out[(size_t)j * R + i] = in[idx];
}

// ---------------------------------------------------------------------------
// Host launcher
// ---------------------------------------------------------------------------
extern "C" void kernel_launch(void* const* d_in, const int* in_sizes, int n_in,
                              void* d_out, int out_size)
{
    (void)in_sizes; (void)n_in; (void)out_size;
    const float* own_obs = (const float*)d_in[0];
    const float* ally    = (const float*)d_in[1];
    const float* enemy   = (const float*)d_in[2];
    const float* hidden  = (const float*)d_in[3];
    const float* Wq   = (const float*)d_in[4];
    const float* bq   = (const float*)d_in[5];
    const float* Wak  = (const float*)d_in[6];
    const float* Wav  = (const float*)d_in[8];
    const float* bav  = (const float*)d_in[9];
    const float* Wek  = (const float*)d_in[10];
    const float* Wev  = (const float*)d_in[12];
    const float* bev  = (const float*)d_in[13];
    const float* Wov  = (const float*)d_in[14];
    const float* bov  = (const float*)d_in[15];
    const float* w_ih = (const float*)d_in[16];
    const float* w_hh = (const float*)d_in[17];
    const float* b_ih = (const float*)d_in[18];
    const float* b_hh = (const float*)d_in[19];
    const float* Wwo  = (const float*)d_in[20];
    const float* bwo  = (const float*)d_in[21];
    const float* We1  = (const float*)d_in[22];
    const float* be1  = (const float*)d_in[23];
    const float* We2  = (const float*)d_in[24];
    const float* be2  = (const float*)d_in[25];
    const float* Wa1  = (const float*)d_in[26];
    const float* ba1  = (const float*)d_in[27];
    const float* Wa2  = (const float*)d_in[28];
    const float* ba2  = (const float*)d_in[29];

    float* out   = (float*)d_out;
    float* h_out = out + (size_t)BSZ * QOUT;

    float *p_query, *p_qa, *p_qe, *p_afw, *p_efw, *p_tot, *p_gi, *p_gh;
    float *p_hterm, *p_M, *p_cvec, *p_wihT, *p_whhT, *p_WakT, *p_WekT, *p_relu1, *p_aqpart;
    cudaGetSymbolAddress((void**)&p_query,  g_query);
    cudaGetSymbolAddress((void**)&p_qa,     g_qa);
    cudaGetSymbolAddress((void**)&p_qe,     g_qe);
    cudaGetSymbolAddress((void**)&p_afw,    g_afw);
    cudaGetSymbolAddress((void**)&p_efw,    g_efw);
    cudaGetSymbolAddress((void**)&p_tot,    g_tot);
    cudaGetSymbolAddress((void**)&p_gi,     g_gi);
    cudaGetSymbolAddress((void**)&p_gh,     g_gh);
    cudaGetSymbolAddress((void**)&p_hterm,  g_hterm);
    cudaGetSymbolAddress((void**)&p_M,      g_M);
    cudaGetSymbolAddress((void**)&p_cvec,   g_cvec);
    cudaGetSymbolAddress((void**)&p_wihT,   g_wihT);
    cudaGetSymbolAddress((void**)&p_whhT,   g_whhT);
    cudaGetSymbolAddress((void**)&p_WakT,   g_WakT);
    cudaGetSymbolAddress((void**)&p_WekT,   g_WekT);
    cudaGetSymbolAddress((void**)&p_relu1,  g_relu1);
    cudaGetSymbolAddress((void**)&p_aqpart, g_aqpart);

    const int T = 256;

    // Weight preprocessing (cheap, per launch; captured into the graph)
    transpose_kernel<<<(1536 * 768 + T - 1) / T, T>>>(w_ih, p_wihT, 1536, 768);
    transpose_kernel<<<(1536 * 512 + T - 1) / T, T>>>(w_hh, p_whhT, 1536, 512);
    transpose_kernel<<<(64 * 128 + T - 1) / T, T>>>(Wak, p_WakT, 64, 128);
    transpose_kernel<<<(65 * 128 + T - 1) / T, T>>>(Wek, p_WekT, 65, 128);
    // M = We2 @ Wa1[:512, :],  cvec = be2 @ Wa1[:512, :] + ba1
    sgemm_kernel<<<dim3(4, 4), T>>>(We2, Wa1, nullptr, p_M, 512, 512, 512, 512, 512, 512, 0);
    cvec_kernel<<<(HDIM * 32 + T - 1) / T, T>>>(be2, Wa1, ba1, p_cvec);

    // Projections
    sgemm_kernel<<<dim3(1, 32), T>>>(own_obs, Wq, bq, p_query, BSZ, ADIM, D_OWN, D_OWN, ADIM, ADIM, 0);
    sgemm_kernel<<<dim3(1, 32), T>>>(p_query, p_WakT, nullptr, p_qa, BSZ, D_AL, ADIM, ADIM, D_AL, D_AL, 0);
    sgemm_kernel<<<dim3(1, 32), T>>>(p_query, p_WekT, nullptr, p_qe, BSZ, D_EN, ADIM, ADIM, D_EN, D_EN, 0);
    // own_hidden -> tot[:, 0:256]
    sgemm_kernel<<<dim3(2, 32), T>>>(own_obs, Wov, bov, p_tot, BSZ, EDIM, D_OWN, D_OWN, EDIM, 3 * EDIM, 0);

    // Attention (softmax over raw features; V projection deferred)
    attn_kernel<D_AL, NALLY><<<BSZ / 8, T>>>(ally, p_qa, p_afw);
    attn_kernel<D_EN, NEN><<<BSZ / 8, T>>>(enemy, p_qe, p_efw);
    sgemm_kernel<<<dim3(2, 32), T>>>(p_afw, Wav, bav, p_tot + EDIM, BSZ, EDIM, D_AL, D_AL, EDIM, 3 * EDIM, 0);
    sgemm_kernel<<<dim3(2, 32), T>>>(p_efw, Wev, bev, p_tot + 2 * EDIM, BSZ, EDIM, D_EN, D_EN, EDIM, 3 * EDIM, 0);

    // GRU
    sgemm_kernel<<<dim3(12, 32), T>>>(p_tot, p_wihT, b_ih, p_gi, BSZ, 3 * HDIM, 3 * EDIM, 3 * EDIM, 3 * HDIM, 3 * HDIM, 0);
    sgemm_kernel<<<dim3(12, 32), T>>>(hidden, p_whhT, b_hh, p_gh, BSZ, 3 * HDIM, HDIM, HDIM, 3 * HDIM, 3 * HDIM, 0);
    gru_gate_kernel<<<(BSZ * HDIM) / T, T>>>(p_gi, p_gh, hidden, h_out);

    // Heads
    woq_kernel<<<(BSZ * NACT + T - 1) / T, T>>>(h_out, Wwo, bwo, out);
    // relu1 = relu(enemy_flat[131072,65] @ We1 + be1)
    sgemm_kernel<<<dim3(4, 1024), T>>>(enemy, We1, be1, p_relu1, M_AQ, HDIM, D_EN, D_EN, HDIM, HDIM, 1);
    // hterm = h @ Wa1[512:, :] + cvec
    sgemm_kernel<<<dim3(4, 32), T>>>(h_out, Wa1 + (size_t)HDIM * HDIM, p_cvec, p_hterm,
                                     BSZ, HDIM, HDIM, HDIM, HDIM, HDIM, 0);
    // aq = relu(relu1 @ M + hterm) @ Wa2  (fused epilogue, column-block partials)
    sgemm_aq_kernel<<<dim3(4, 1024), T>>>(p_relu1, p_M, p_hterm, Wa2, p_aqpart);
    aqfin_kernel<<<M_AQ / T, T>>>(p_aqpart, ba2, out);
}

// round 5
// speedup vs baseline: 1.9507x; 1.9507x over previous
#include <cuda_runtime.h>
#include <cstddef>
#include <cstdint>

// ---------------------------------------------------------------------------
// Problem constants
// ---------------------------------------------------------------------------
#define BSZ   4096
#define NALLY 31
#define NEN   32
#define D_OWN 128
#define D_AL  64
#define D_EN  65
#define ADIM  128
#define EDIM  256
#define HDIM  512
#define NACT  6
#define QOUT  (NACT + NEN)   // 38
#define M_AQ  (NEN * BSZ)    // 131072

// ---------------------------------------------------------------------------
// Scratch (static device globals; no runtime allocation)
// ---------------------------------------------------------------------------
__device__ float g_query [BSZ * ADIM];
__device__ float g_qa    [BSZ * D_AL];
__device__ float g_qe    [BSZ * D_EN];
__device__ float g_afw   [BSZ * D_AL];
__device__ float g_efw   [BSZ * D_EN];
__device__ float g_tot   [BSZ * 3 * EDIM];          // [B,768]
__device__ float g_gi    [BSZ * 3 * HDIM];
__device__ float g_gh    [BSZ * 3 * HDIM];
__device__ float g_hterm [BSZ * HDIM];
__device__ float g_M     [HDIM * HDIM];
__device__ float g_Mt    [HDIM * HDIM];
__device__ float g_cvec  [HDIM];
__device__ float g_WakT  [ADIM * D_AL];
__device__ float g_WekT  [ADIM * D_EN];
__device__ float g_We1T  [HDIM * D_EN];
__device__ float g_Wa1botT [HDIM * HDIM];
__device__ float g_relu1 [(size_t)M_AQ * HDIM];     // 268 MB
__device__ float g_aqpart[M_AQ];

// ---------------------------------------------------------------------------
// Portable PTX helpers (sm_80-family features only; NO tcgen05)
// ---------------------------------------------------------------------------
__device__ __forceinline__ uint32_t smem_u32(const void* p) {
    return (uint32_t)__cvta_generic_to_shared(p);
}

#define CP_ASYNC16(dst, src) \
    asm volatile("cp.async.cg.shared.global [%0], [%1], 16;" :: "r"(dst), "l"(src))
#define CP_COMMIT() asm volatile("cp.async.commit_group;")
template <int N>
__device__ __forceinline__ void cp_wait() {
    asm volatile("cp.async.wait_group %0;" :: "n"(N));
}

__device__ __forceinline__ uint32_t f2tf32(float x) {
    uint32_t r;
    asm("cvt.rna.tf32.f32 %0, %1;" : "=r"(r) : "f"(x));
    return r;
}

__device__ __forceinline__ void mma_tf32(float* c,
                                         uint32_t a0, uint32_t a1, uint32_t a2, uint32_t a3,
                                         uint32_t b0, uint32_t b1) {
    asm volatile(
        "mma.sync.aligned.m16n8k8.row.col.f32.tf32.tf32.f32 "
        "{%0,%1,%2,%3}, {%4,%5,%6,%7}, {%8,%9}, {%0,%1,%2,%3};"
        : "+f"(c[0]), "+f"(c[1]), "+f"(c[2]), "+f"(c[3])
        : "r"(a0), "r"(a1), "r"(a2), "r"(a3), "r"(b0), "r"(b1));
}

// ---------------------------------------------------------------------------
// Tensor-core GEMM via mma.sync, 3xTF32 split for ~fp32 accuracy:
//   x = hi + lo (hi = rna-tf32(x), lo = rna-tf32(x - hi));
//   acc += a_hi*b_lo + a_lo*b_hi + a_hi*b_hi  (lo*lo dropped, ~2^-22)
//   C[m, n] = sum_k A[m,k] * B[n,k]  (+bias[n]) (+relu)
// BM=BN=128, BK=16. 256 threads = 8 warps (4 m x 2 n); warp tile 32x64.
// SMEM [row][k] stride 20 floats: conflict-free fragment LDS + 16B cp.async rows.
// SCALAR=1: guarded scalar global loads (for K not mult of 16 / unaligned lda).
// AQ=1: fused epilogue p[row] += relu(c + hterm[row%B, col]) * Wa2[col],
//       quad-reduced and atomicAdd'ed into C (= aqpart, pre-zeroed).
// ---------------------------------------------------------------------------
template <int SCALAR, int AQ, int SPLIT>
__global__ void __launch_bounds__(256)
mma_gemm_kernel(const float* __restrict__ A, const float* __restrict__ B,
                const float* __restrict__ bias, float* __restrict__ C,
                const float* __restrict__ hterm, const float* __restrict__ Wa2,
                int K, int lda, int ldb, int ldc, int relu)
{
    __shared__ __align__(16) float As[2][128][20];
    __shared__ __align__(16) float Bs[2][128][20];

    const int tid = threadIdx.x;
    const int lane = tid & 31, wid = tid >> 5;
    const int warpM = wid & 3, warpN = wid >> 2;
    const int gid = lane >> 2, tg = lane & 3;
    const int rowBase = blockIdx.y * 128;
    const int colBase = blockIdx.x * 128;

    float acc[2][8][4];
#pragma unroll
    for (int mt = 0; mt < 2; mt++)
#pragma unroll
        for (int nt = 0; nt < 8; nt++)
#pragma unroll
            for (int i = 0; i < 4; i++) acc[mt][nt][i] = 0.f;

    const int nSlices = (K + 15) >> 4;

    auto compute = [&](int buf) {
#pragma unroll
        for (int ks = 0; ks < 2; ks++) {
            const int kk = ks * 8;
            // A fragments: hi + lo in registers
            uint32_t ah[2][4], al[2][4];
#pragma unroll
            for (int mt = 0; mt < 2; mt++) {
                int m = warpM * 32 + mt * 16 + gid;
                float a0 = As[buf][m][kk + tg];
                float a1 = As[buf][m + 8][kk + tg];
                float a2 = As[buf][m][kk + tg + 4];
                float a3 = As[buf][m + 8][kk + tg + 4];
                ah[mt][0] = f2tf32(a0); ah[mt][1] = f2tf32(a1);
                ah[mt][2] = f2tf32(a2); ah[mt][3] = f2tf32(a3);
                if (SPLIT) {
                    al[mt][0] = f2tf32(a0 - __uint_as_float(ah[mt][0]));
                    al[mt][1] = f2tf32(a1 - __uint_as_float(ah[mt][1]));
                    al[mt][2] = f2tf32(a2 - __uint_as_float(ah[mt][2]));
                    al[mt][3] = f2tf32(a3 - __uint_as_float(ah[mt][3]));
                }
            }
#pragma unroll
            for (int nt = 0; nt < 8; nt++) {
                int n = warpN * 64 + nt * 8 + gid;
                float b0 = Bs[buf][n][kk + tg];
                float b1 = Bs[buf][n][kk + tg + 4];
                uint32_t bh0 = f2tf32(b0), bh1 = f2tf32(b1);
                uint32_t bl0 = 0, bl1 = 0;
                if (SPLIT) {
                    bl0 = f2tf32(b0 - __uint_as_float(bh0));
                    bl1 = f2tf32(b1 - __uint_as_float(bh1));
                }
#pragma unroll
                for (int mt = 0; mt < 2; mt++) {
                    if (SPLIT) {
                        mma_tf32(acc[mt][nt], ah[mt][0], ah[mt][1], ah[mt][2], ah[mt][3], bl0, bl1);
                        mma_tf32(acc[mt][nt], al[mt][0], al[mt][1], al[mt][2], al[mt][3], bh0, bh1);
                    }
                    mma_tf32(acc[mt][nt], ah[mt][0], ah[mt][1], ah[mt][2], ah[mt][3], bh0, bh1);
                }
            }
        }
    };

    if (!SCALAR) {
        // cp.async double-buffered pipeline (requires K%16==0, 16B-aligned rows)
        {
            const int k0 = 0;
#pragma unroll
            for (int t = 0; t < 2; t++) {
                int task = t * 256 + tid;          // 0..511
                int r = task >> 2, seg = task & 3;
                CP_ASYNC16(smem_u32(&As[0][r][seg * 4]),
                           A + (size_t)(rowBase + r) * lda + k0 + seg * 4);
                CP_ASYNC16(smem_u32(&Bs[0][r][seg * 4]),
                           B + (size_t)(colBase + r) * ldb + k0 + seg * 4);
            }
            CP_COMMIT();
        }
        for (int kc = 0; kc < nSlices; kc++) {
            if (kc + 1 < nSlices) {
                const int k0 = (kc + 1) * 16;
                const int buf = (kc + 1) & 1;
#pragma unroll
                for (int t = 0; t < 2; t++) {
                    int task = t * 256 + tid;
                    int r = task >> 2, seg = task & 3;
                    CP_ASYNC16(smem_u32(&As[buf][r][seg * 4]),
                               A + (size_t)(rowBase + r) * lda + k0 + seg * 4);
                    CP_ASYNC16(smem_u32(&Bs[buf][r][seg * 4]),
                               B + (size_t)(colBase + r) * ldb + k0 + seg * 4);
                }
                CP_COMMIT();
                cp_wait<1>();
            } else {
                cp_wait<0>();
            }
            __syncthreads();
            compute(kc & 1);
            __syncthreads();
        }
    } else {
        // guarded scalar path (K=65 etc.)
        for (int kc = 0; kc < nSlices; kc++) {
            const int k0 = kc * 16;
            for (int i = tid; i < 128 * 16; i += 256) {
                int r = i >> 4, k = i & 15, gk = k0 + k;
                As[0][r][k] = (gk < K) ? A[(size_t)(rowBase + r) * lda + gk] : 0.f;
                Bs[0][r][k] = (gk < K) ? B[(size_t)(colBase + r) * ldb + gk] : 0.f;
            }
            __syncthreads();
            compute(0);
            __syncthreads();
        }
    }

    if (!AQ) {
#pragma unroll
        for (int mt = 0; mt < 2; mt++) {
            int r0 = rowBase + warpM * 32 + mt * 16 + gid;
#pragma unroll
            for (int nt = 0; nt < 8; nt++) {
                int cc = colBase + warpN * 64 + nt * 8 + 2 * tg;
                float b0v = bias ? __ldg(bias + cc) : 0.f;
                float b1v = bias ? __ldg(bias + cc + 1) : 0.f;
                float v0 = acc[mt][nt][0] + b0v, v1 = acc[mt][nt][1] + b1v;
                float v2 = acc[mt][nt][2] + b0v, v3 = acc[mt][nt][3] + b1v;
                if (relu) {
                    v0 = fmaxf(v0, 0.f); v1 = fmaxf(v1, 0.f);
                    v2 = fmaxf(v2, 0.f); v3 = fmaxf(v3, 0.f);
                }
                float2 w0 = make_float2(v0, v1);
                float2 w1 = make_float2(v2, v3);
                *(float2*)&C[(size_t)r0 * ldc + cc] = w0;
                *(float2*)&C[(size_t)(r0 + 8) * ldc + cc] = w1;
            }
        }
    } else {
        float p[2][2] = {{0.f, 0.f}, {0.f, 0.f}};
#pragma unroll
        for (int mt = 0; mt < 2; mt++) {
            int r0 = rowBase + warpM * 32 + mt * 16 + gid;
            const float* h0 = hterm + (size_t)(r0 & (BSZ - 1)) * HDIM;
            const float* h1 = hterm + (size_t)((r0 + 8) & (BSZ - 1)) * HDIM;
#pragma unroll
            for (int nt = 0; nt < 8; nt++) {
                int cc = colBase + warpN * 64 + nt * 8 + 2 * tg;
                float w0 = __ldg(Wa2 + cc), w1 = __ldg(Wa2 + cc + 1);
                p[mt][0] += fmaxf(acc[mt][nt][0] + __ldg(h0 + cc), 0.f) * w0
                          + fmaxf(acc[mt][nt][1] + __ldg(h0 + cc + 1), 0.f) * w1;
                p[mt][1] += fmaxf(acc[mt][nt][2] + __ldg(h1 + cc), 0.f) * w0
                          + fmaxf(acc[mt][nt][3] + __ldg(h1 + cc + 1), 0.f) * w1;
            }
        }
        // reduce over the 4 lanes of each quad (same row, different tg)
#pragma unroll
        for (int mt = 0; mt < 2; mt++)
#pragma unroll
            for (int j = 0; j < 2; j++) {
                p[mt][j] += __shfl_xor_sync(0xffffffffu, p[mt][j], 1);
                p[mt][j] += __shfl_xor_sync(0xffffffffu, p[mt][j], 2);
            }
        if (tg == 0) {
#pragma unroll
            for (int mt = 0; mt < 2; mt++) {
                int r0 = rowBase + warpM * 32 + mt * 16 + gid;
                atomicAdd(&C[r0], p[mt][0]);
                atomicAdd(&C[r0 + 8], p[mt][1]);
            }
        }
    }
}

// ---------------------------------------------------------------------------
// SIMT SGEMM (small ops): C[M,N] = A[M,K] @ B[K,N] (+bias) (+relu)
// ---------------------------------------------------------------------------
__global__ void sgemm_kernel(const float* __restrict__ A, const float* __restrict__ Bm,
                             const float* __restrict__ bias, float* __restrict__ C,
                             int M, int N, int K, int lda, int ldb, int ldc, int relu)
{
    constexpr int BM = 128, BN = 128, BK = 8, TM = 8, TN = 8;
    __shared__ float As[BK][BM];
    __shared__ float Bs[BK][BN];

    const int tid = threadIdx.x;
    const int tx = tid & 15, ty = tid >> 4;
    const int rowBase = blockIdx.y * BM;
    const int colBase = blockIdx.x * BN;

    float acc[TM][TN];
#pragma unroll
    for (int i = 0; i < TM; i++)
#pragma unroll
        for (int j = 0; j < TN; j++) acc[i][j] = 0.f;

    const int aRow = tid >> 1, aCol = (tid & 1) * 4;
    const int bRow = tid >> 5, bCol = (tid & 31) * 4;

    for (int k0 = 0; k0 < K; k0 += BK) {
#pragma unroll
        for (int i = 0; i < 4; i++) {
            int k = k0 + aCol + i;
            int m = rowBase + aRow;
            As[aCol + i][aRow] = (m < M && k < K) ? __ldg(&A[(size_t)m * lda + k]) : 0.f;
        }
#pragma unroll
        for (int i = 0; i < 4; i++) {
            int k = k0 + bRow;
            int n = colBase + bCol + i;
            Bs[bRow][bCol + i] = (k < K && n < N) ? __ldg(&Bm[(size_t)k * ldb + n]) : 0.f;
        }
        __syncthreads();
#pragma unroll
        for (int kk = 0; kk < BK; kk++) {
            float a[TM], b[TN];
#pragma unroll
            for (int i = 0; i < TM; i++) a[i] = As[kk][ty * TM + i];
#pragma unroll
            for (int j = 0; j < TN; j++) b[j] = Bs[kk][tx * TN + j];
#pragma unroll
            for (int i = 0; i < TM; i++)
#pragma unroll
                for (int j = 0; j < TN; j++) acc[i][j] += a[i] * b[j];
        }
        __syncthreads();
    }

#pragma unroll
    for (int i = 0; i < TM; i++) {
        int r = rowBase + ty * TM + i;
        if (r >= M) continue;
#pragma unroll
        for (int j = 0; j < TN; j++) {
            int c = colBase + tx * TN + j;
            if (c >= N) continue;
            float v = acc[i][j];
            if (bias) v += __ldg(&bias[c]);
            if (relu) v = fmaxf(v, 0.f);
            C[(size_t)r * ldc + c] = v;
        }
    }
}

// ---------------------------------------------------------------------------
// Attention: one warp per batch element (softmax over raw features).
// ---------------------------------------------------------------------------
template <int D, int Nn>
__global__ void attn_kernel(const float* __restrict__ feats,   // [Nn, B, D]
                            const float* __restrict__ qproj,   // [B, D]
                            float* __restrict__ fw)            // [B, D]
{
    constexpr int NC = (D + 31) / 32;
    const int warp = (blockIdx.x * blockDim.x + threadIdx.x) >> 5;
    const int lane = threadIdx.x & 31;
    if (warp >= BSZ) return;
    const int b = warp;

    float qv[NC];
#pragma unroll
    for (int c = 0; c < NC; c++) {
        int d = lane + c * 32;
        qv[c] = (d < D) ? qproj[(size_t)b * D + d] : 0.f;
    }

    const float scale = rsqrtf((float)ADIM);
    float myE = 0.f, m = -1e30f;
    for (int n = 0; n < Nn; n++) {
        const float* f = feats + ((size_t)n * BSZ + b) * D;
        float p = 0.f;
#pragma unroll
        for (int c = 0; c < NC; c++) {
            int d = lane + c * 32;
            if (d < D) p += f[d] * qv[c];
        }
#pragma unroll
        for (int o = 16; o; o >>= 1) p += __shfl_xor_sync(0xffffffffu, p, o);
        p *= scale;
        if (lane == n) myE = p;
        m = fmaxf(m, p);
    }
    float wgt = (lane < Nn) ? expf(myE - m) : 0.f;
    float s = wgt;
#pragma unroll
    for (int o = 16; o; o >>= 1) s += __shfl_xor_sync(0xffffffffu, s, o);
    const float attnW = wgt / s;

    float acc[NC];
#pragma unroll
    for (int c = 0; c < NC; c++) acc[c] = 0.f;
    for (int n = 0; n < Nn; n++) {
        float a = __shfl_sync(0xffffffffu, attnW, n);
        const float* f = feats + ((size_t)n * BSZ + b) * D;
#pragma unroll
        for (int c = 0; c < NC; c++) {
            int d = lane + c * 32;
            if (d < D) acc[c] += a * f[d];
        }
    }
#pragma unroll
    for (int c = 0; c < NC; c++) {
        int d = lane + c * 32;
        if (d < D) fw[(size_t)b * D + d] = acc[c];
    }
}

// GRU gate fusion
__global__ void gru_gate_kernel(const float* __restrict__ gi, const float* __restrict__ gh,
                                const float* __restrict__ hprev, float* __restrict__ hout)
{
    int idx = blockIdx.x * blockDim.x + threadIdx.x;
    if (idx >= BSZ * HDIM) return;
    int b = idx >> 9, k = idx & (HDIM - 1);
    const float* gib = gi + (size_t)b * 3 * HDIM;
    const float* ghb = gh + (size_t)b * 3 * HDIM;
    float ir = gib[k], iz = gib[HDIM + k], in_ = gib[2 * HDIM + k];
    float hr = ghb[k], hz = ghb[HDIM + k], hn  = ghb[2 * HDIM + k];
    float r = 1.f / (1.f + expf(-(ir + hr)));
    float z = 1.f / (1.f + expf(-(iz + hz)));
    float n = tanhf(in_ + r * hn);
    hout[idx] = (1.f - z) * n + z * hprev[idx];
}

// wo_q head
__global__ void woq_kernel(const float* __restrict__ h, const float* __restrict__ Wwo,
                           const float* __restrict__ bwo, float* __restrict__ out)
{
    int idx = blockIdx.x * blockDim.x + threadIdx.x;
    if (idx >= BSZ * NACT) return;
    int b = idx / NACT, j = idx - b * NACT;
    const float* hb = h + (size_t)b * HDIM;
    float s = bwo[j];
#pragma unroll 8
    for (int k = 0; k < HDIM; k++) s += hb[k] * __ldg(&Wwo[k * NACT + j]);
    out[(size_t)b * QOUT + j] = s;
}

// aq finish: out[b, 6+n] = aqpart[n*B + b] + ba2
__global__ void aqfin_kernel(const float* __restrict__ part, const float* __restrict__ ba2,
                             float* __restrict__ out)
{
    int idx = blockIdx.x * blockDim.x + threadIdx.x;
    if (idx >= M_AQ) return;
    int n = idx >> 12, b = idx & (BSZ - 1);
    out[(size_t)b * QOUT + NACT + n] = part[idx] + __ldg(ba2);
}

// cvec[j] = be2 @ Wa1_top[:, j] + ba1[j]
__global__ void cvec_kernel(const float* __restrict__ be2, const float* __restrict__ Wa1,
                            const float* __restrict__ ba1, float* __restrict__ cvec)
{
    int warp = (blockIdx.x * blockDim.x + threadIdx.x) >> 5;
    int lane = threadIdx.x & 31;
    if (warp >= HDIM) return;
    float s = 0.f;
    for (int k = lane; k < HDIM; k += 32) s += be2[k] * Wa1[(size_t)k * HDIM + warp];
#pragma unroll
    for (int o = 16; o; o >>= 1) s += __shfl_xor_sync(0xffffffffu, s, o);
    if (lane == 0) cvec[warp] = s + ba1[warp];
}

// naive transpose: out[j, i] = in[i, j]  for in[R, C]
__global__ void transpose_kernel(const float* __restrict__ in, float* __restrict__ out,
                                 int R, int C)
{
    int idx = blockIdx.x * blockDim.x + threadIdx.x;
    if (idx >= R * C) return;
    int i = idx / C, j = idx - i * C;
    out[(size_t)j * R + i] = in[idx];
}

// ---------------------------------------------------------------------------
// Host launcher
// ---------------------------------------------------------------------------
extern "C" void kernel_launch(void* const* d_in, const int* in_sizes, int n_in,
                              void* d_out, int out_size)
{
    (void)in_sizes; (void)n_in; (void)out_size;
    const float* own_obs = (const float*)d_in[0];
    const float* ally    = (const float*)d_in[1];
    const float* enemy   = (const float*)d_in[2];
    const float* hidden  = (const float*)d_in[3];
    const float* Wq   = (const float*)d_in[4];
    const float* bq   = (const float*)d_in[5];
    const float* Wak  = (const float*)d_in[6];
    const float* Wav  = (const float*)d_in[8];
    const float* bav  = (const float*)d_in[9];
    const float* Wek  = (const float*)d_in[10];
    const float* Wev  = (const float*)d_in[12];
    const float* bev  = (const float*)d_in[13];
    const float* Wov  = (const float*)d_in[14];
    const float* bov  = (const float*)d_in[15];
    const float* w_ih = (const float*)d_in[16];
    const float* w_hh = (const float*)d_in[17];
    const float* b_ih = (const float*)d_in[18];
    const float* b_hh = (const float*)d_in[19];
    const float* Wwo  = (const float*)d_in[20];
    const float* bwo  = (const float*)d_in[21];
    const float* We1  = (const float*)d_in[22];
    const float* be1  = (const float*)d_in[23];
    const float* We2  = (const float*)d_in[24];
    const float* be2  = (const float*)d_in[25];
    const float* Wa1  = (const float*)d_in[26];
    const float* ba1  = (const float*)d_in[27];
    const float* Wa2  = (const float*)d_in[28];
    const float* ba2  = (const float*)d_in[29];

    float* out   = (float*)d_out;
    float* h_out = out + (size_t)BSZ * QOUT;

    float *p_query, *p_qa, *p_qe, *p_afw, *p_efw, *p_tot, *p_gi, *p_gh;
    float *p_hterm, *p_M, *p_Mt, *p_cvec, *p_WakT, *p_WekT, *p_We1T, *p_Wa1botT;
    float *p_relu1, *p_aqpart;
    cudaGetSymbolAddress((void**)&p_query,   g_query);
    cudaGetSymbolAddress((void**)&p_qa,      g_qa);
    cudaGetSymbolAddress((void**)&p_qe,      g_qe);
    cudaGetSymbolAddress((void**)&p_afw,     g_afw);
    cudaGetSymbolAddress((void**)&p_efw,     g_efw);
    cudaGetSymbolAddress((void**)&p_tot,     g_tot);
    cudaGetSymbolAddress((void**)&p_gi,      g_gi);
    cudaGetSymbolAddress((void**)&p_gh,      g_gh);
    cudaGetSymbolAddress((void**)&p_hterm,   g_hterm);
    cudaGetSymbolAddress((void**)&p_M,       g_M);
    cudaGetSymbolAddress((void**)&p_Mt,      g_Mt);
    cudaGetSymbolAddress((void**)&p_cvec,    g_cvec);
    cudaGetSymbolAddress((void**)&p_WakT,    g_WakT);
    cudaGetSymbolAddress((void**)&p_WekT,    g_WekT);
    cudaGetSymbolAddress((void**)&p_We1T,    g_We1T);
    cudaGetSymbolAddress((void**)&p_Wa1botT, g_Wa1botT);
    cudaGetSymbolAddress((void**)&p_relu1,   g_relu1);
    cudaGetSymbolAddress((void**)&p_aqpart,  g_aqpart);

    const int T = 256;

    // --- weight preprocessing ---
    transpose_kernel<<<(64 * 128 + T - 1) / T, T>>>(Wak, p_WakT, 64, 128);
    transpose_kernel<<<(65 * 128 + T - 1) / T, T>>>(Wek, p_WekT, 65, 128);
    transpose_kernel<<<(65 * 512 + T - 1) / T, T>>>(We1, p_We1T, 65, 512);
    transpose_kernel<<<(512 * 512 + T - 1) / T, T>>>(Wa1 + (size_t)HDIM * HDIM, p_Wa1botT, 512, 512);
    // M = We2 @ Wa1_top ; Mt = M^T ; cvec
    sgemm_kernel<<<dim3(4, 4), T>>>(We2, Wa1, nullptr, p_M, 512, 512, 512, 512, 512, 512, 0);
    transpose_kernel<<<(512 * 512 + T - 1) / T, T>>>(p_M, p_Mt, 512, 512);
    cvec_kernel<<<(HDIM * 32 + T - 1) / T, T>>>(be2, Wa1, ba1, p_cvec);

    // --- projections (SIMT, small) ---
    sgemm_kernel<<<dim3(1, 32), T>>>(own_obs, Wq, bq, p_query, BSZ, ADIM, D_OWN, D_OWN, ADIM, ADIM, 0);
    sgemm_kernel<<<dim3(1, 32), T>>>(p_query, p_WakT, nullptr, p_qa, BSZ, D_AL, ADIM, ADIM, D_AL, D_AL, 0);
    sgemm_kernel<<<dim3(1, 32), T>>>(p_query, p_WekT, nullptr, p_qe, BSZ, D_EN, ADIM, ADIM, D_EN, D_EN, 0);
    sgemm_kernel<<<dim3(2, 32), T>>>(own_obs, Wov, bov, p_tot, BSZ, EDIM, D_OWN, D_OWN, EDIM, 3 * EDIM, 0);

    // --- attention ---
    attn_kernel<D_AL, NALLY><<<BSZ / 8, T>>>(ally, p_qa, p_afw);
    attn_kernel<D_EN, NEN><<<BSZ / 8, T>>>(enemy, p_qe, p_efw);
    sgemm_kernel<<<dim3(2, 32), T>>>(p_afw, Wav, bav, p_tot + EDIM, BSZ, EDIM, D_AL, D_AL, EDIM, 3 * EDIM, 0);
    sgemm_kernel<<<dim3(2, 32), T>>>(p_efw, Wev, bev, p_tot + 2 * EDIM, BSZ, EDIM, D_EN, D_EN, EDIM, 3 * EDIM, 0);

    // --- GRU (3xTF32 mma.sync; w_ih/w_hh natively [N,K]) ---
    mma_gemm_kernel<0, 0, 1><<<dim3(12, 32), 256>>>(p_tot, w_ih, b_ih, p_gi,
                                                    nullptr, nullptr, 3 * EDIM, 3 * EDIM, 3 * EDIM, 3 * HDIM, 0);
    mma_gemm_kernel<0, 0, 1><<<dim3(12, 32), 256>>>(hidden, w_hh, b_hh, p_gh,
                                                    nullptr, nullptr, HDIM, HDIM, HDIM, 3 * HDIM, 0);
    gru_gate_kernel<<<(BSZ * HDIM) / T, T>>>(p_gi, p_gh, hidden, h_out);

    // --- heads ---
    woq_kernel<<<(BSZ * NACT + T - 1) / T, T>>>(h_out, Wwo, bwo, out);
    // relu1 = relu(enemy_flat[131072,65] @ We1 + be1)  (K=65 -> guarded scalar loads)
    mma_gemm_kernel<1, 0, 1><<<dim3(4, 1024), 256>>>(enemy, p_We1T, be1, p_relu1,
                                                     nullptr, nullptr, D_EN, D_EN, D_EN, HDIM, 1);
    // hterm = h @ Wa1_bot + cvec
    mma_gemm_kernel<0, 0, 1><<<dim3(4, 32), 256>>>(h_out, p_Wa1botT, p_cvec, p_hterm,
                                                   nullptr, nullptr, HDIM, HDIM, HDIM, HDIM, 0);
    // aq = relu(relu1 @ M + hterm) @ Wa2 + ba2  (fused epilogue into aqpart)
    cudaMemsetAsync(p_aqpart, 0, (size_t)M_AQ * sizeof(float), 0);
    mma_gemm_kernel<0, 1, 1><<<dim3(4, 1024), 256>>>(p_relu1, p_Mt, nullptr, p_aqpart,
                                                     p_hterm, Wa2, HDIM, HDIM, HDIM, 0, 0);
    aqfin_kernel<<<M_AQ / T, T>>>(p_aqpart, ba2, out);
}

// round 6
// speedup vs baseline: 2.3267x; 1.1928x over previous
#include <cuda_runtime.h>
#include <cstddef>
#include <cstdint>

// ---------------------------------------------------------------------------
// Problem constants
// ---------------------------------------------------------------------------
#define BSZ   4096
#define NALLY 31
#define NEN   32
#define D_OWN 128
#define D_AL  64
#define D_EN  65
#define ADIM  128
#define EDIM  256
#define HDIM  512
#define NACT  6
#define QOUT  (NACT + NEN)   // 38
#define M_AQ  (NEN * BSZ)    // 131072

// ---------------------------------------------------------------------------
// Scratch (static device globals; no runtime allocation)
// ---------------------------------------------------------------------------
__device__ float g_query [BSZ * ADIM];
__device__ float g_qa    [BSZ * D_AL];
__device__ float g_qe    [BSZ * D_EN];
__device__ float g_afw   [BSZ * D_AL];
__device__ float g_efw   [BSZ * D_EN];
__device__ float g_tot   [BSZ * 3 * EDIM];          // [B,768]
__device__ float g_gi    [BSZ * 3 * HDIM];
__device__ float g_gh    [BSZ * 3 * HDIM];
__device__ float g_hterm [BSZ * HDIM];
__device__ float g_M     [HDIM * HDIM];
__device__ float g_Mt    [HDIM * HDIM];
__device__ float g_cvec  [HDIM];
__device__ float g_WakT  [ADIM * D_AL];
__device__ float g_WekT  [ADIM * D_EN];
__device__ float g_We1T  [HDIM * D_EN];
__device__ float g_Wa1botT [HDIM * HDIM];
__device__ float g_relu1 [(size_t)M_AQ * HDIM];     // 268 MB
__device__ float g_aqpart[M_AQ];

// ---------------------------------------------------------------------------
// bf16 split helpers: x = hi + lo, each bf16; dropped lo*lo term ~2^-18 rel.
// Pack pairs (even k, odd k) into bf16x2 regs matching m16n8k16 fragments.
// ---------------------------------------------------------------------------
__device__ __forceinline__ uint2 split_pair(float f0, float f1) {
    uint32_t h;
    asm("cvt.rn.bf16x2.f32 %0, %1, %2;" : "=r"(h) : "f"(f1), "f"(f0));  // lo16=f0, hi16=f1
    float h0 = __uint_as_float(h << 16);
    float h1 = __uint_as_float(h & 0xffff0000u);
    uint32_t l;
    asm("cvt.rn.bf16x2.f32 %0, %1, %2;" : "=r"(l) : "f"(f1 - h1), "f"(f0 - h0));
    return make_uint2(h, l);
}

__device__ __forceinline__ void mma_bf16(float* c, const uint32_t* a,
                                         uint32_t b0, uint32_t b1) {
    asm volatile(
        "mma.sync.aligned.m16n8k16.row.col.f32.bf16.bf16.f32 "
        "{%0,%1,%2,%3}, {%4,%5,%6,%7}, {%8,%9}, {%0,%1,%2,%3};"
        : "+f"(c[0]), "+f"(c[1]), "+f"(c[2]), "+f"(c[3])
        : "r"(a[0]), "r"(a[1]), "r"(a[2]), "r"(a[3]), "r"(b0), "r"(b1));
}

// ---------------------------------------------------------------------------
// Tensor-core GEMM via mma.sync m16n8k16 bf16 with 3-term split (~fp32 acc):
//   acc += a_hi*b_hi + a_hi*b_lo + a_lo*b_hi   (lo*lo dropped)
//   C[m, n] = sum_k A[m,k] * B[n,k]  (+bias[n]) (+relu)
// BM=BN=128, BK=16. 256 threads = 8 warps (4 m x 2 n); warp tile 32x64.
// SMEM: hi/lo bf16x2 planes, [row][kpair] with row stride 12 u32 (perfect
// bank permutation for fragment loads: (gid*12+tg) mod 32 covers all banks).
// Values are split ONCE per block at load time (not per consuming warp).
// Vec path: register-staged LDG prefetch + double buffer, 1 sync/slice.
// SCALAR=1: guarded scalar loads (K=65 etc.), single buffer.
// AQ=1: fused epilogue p[row] += relu(c + hterm[row%B, col]) * Wa2[col],
//       quad-reduced + atomicAdd into C (= aqpart, pre-zeroed).
// ---------------------------------------------------------------------------
template <int SCALAR, int AQ>
__global__ void __launch_bounds__(256)
mma_bf16_gemm(const float* __restrict__ A, const float* __restrict__ B,
              const float* __restrict__ bias, float* __restrict__ C,
              const float* __restrict__ hterm, const float* __restrict__ Wa2,
              int K, int lda, int ldb, int ldc, int relu)
{
    // [buf][A=0/B=1][hi=0/lo=1][row][kpair(+pad)]
    __shared__ uint32_t sm[2][2][2][128][12];

    const int tid = threadIdx.x;
    const int lane = tid & 31, wid = tid >> 5;
    const int warpM = wid & 3, warpN = wid >> 2;
    const int gid = lane >> 2, tg = lane & 3;
    const int rowBase = blockIdx.y * 128;
    const int colBase = blockIdx.x * 128;

    float acc[2][8][4];
#pragma unroll
    for (int mt = 0; mt < 2; mt++)
#pragma unroll
        for (int nt = 0; nt < 8; nt++)
#pragma unroll
            for (int i = 0; i < 4; i++) acc[mt][nt][i] = 0.f;

    const int nSlices = (K + 15) >> 4;

    auto compute = [&](int buf) {
        uint32_t ah[2][4], al[2][4];
#pragma unroll
        for (int mt = 0; mt < 2; mt++) {
            int m = warpM * 32 + mt * 16 + gid;
            ah[mt][0] = sm[buf][0][0][m][tg];     al[mt][0] = sm[buf][0][1][m][tg];
            ah[mt][1] = sm[buf][0][0][m + 8][tg]; al[mt][1] = sm[buf][0][1][m + 8][tg];
            ah[mt][2] = sm[buf][0][0][m][tg + 4]; al[mt][2] = sm[buf][0][1][m][tg + 4];
            ah[mt][3] = sm[buf][0][0][m + 8][tg + 4]; al[mt][3] = sm[buf][0][1][m + 8][tg + 4];
        }
#pragma unroll
        for (int nt = 0; nt < 8; nt++) {
            int n = warpN * 64 + nt * 8 + gid;
            uint32_t bh0 = sm[buf][1][0][n][tg], bh1 = sm[buf][1][0][n][tg + 4];
            uint32_t bl0 = sm[buf][1][1][n][tg], bl1 = sm[buf][1][1][n][tg + 4];
#pragma unroll
            for (int mt = 0; mt < 2; mt++) {
                mma_bf16(acc[mt][nt], ah[mt], bh0, bh1);
                mma_bf16(acc[mt][nt], ah[mt], bl0, bl1);
                mma_bf16(acc[mt][nt], al[mt], bh0, bh1);
            }
        }
    };

    if (!SCALAR) {
        // vec path: K%16==0, rows 16B-aligned. reg-staged prefetch + dbl buffer.
        const int r = tid >> 1;
        const int ph = (tid & 1) * 4;          // kpair base; k offset = ph*2
        float4 va0, va1, vb0, vb1;

        auto ldg_slice = [&](int k0) {
            const float* ap = A + (size_t)(rowBase + r) * lda + k0 + ph * 2;
            va0 = *(const float4*)ap;
            va1 = *(const float4*)(ap + 4);
            const float* bp = B + (size_t)(colBase + r) * ldb + k0 + ph * 2;
            vb0 = *(const float4*)bp;
            vb1 = *(const float4*)(bp + 4);
        };
        auto sts_slice = [&](int buf) {
            uint2 s;
            s = split_pair(va0.x, va0.y); sm[buf][0][0][r][ph+0] = s.x; sm[buf][0][1][r][ph+0] = s.y;
            s = split_pair(va0.z, va0.w); sm[buf][0][0][r][ph+1] = s.x; sm[buf][0][1][r][ph+1] = s.y;
            s = split_pair(va1.x, va1.y); sm[buf][0][0][r][ph+2] = s.x; sm[buf][0][1][r][ph+2] = s.y;
            s = split_pair(va1.z, va1.w); sm[buf][0][0][r][ph+3] = s.x; sm[buf][0][1][r][ph+3] = s.y;
            s = split_pair(vb0.x, vb0.y); sm[buf][1][0][r][ph+0] = s.x; sm[buf][1][1][r][ph+0] = s.y;
            s = split_pair(vb0.z, vb0.w); sm[buf][1][0][r][ph+1] = s.x; sm[buf][1][1][r][ph+1] = s.y;
            s = split_pair(vb1.x, vb1.y); sm[buf][1][0][r][ph+2] = s.x; sm[buf][1][1][r][ph+2] = s.y;
            s = split_pair(vb1.z, vb1.w); sm[buf][1][0][r][ph+3] = s.x; sm[buf][1][1][r][ph+3] = s.y;
        };

        ldg_slice(0);
        for (int kc = 0; kc < nSlices; kc++) {
            sts_slice(kc & 1);
            if (kc + 1 < nSlices) ldg_slice((kc + 1) * 16);   // prefetch under MMAs
            __syncthreads();
            compute(kc & 1);
        }
    } else {
        // guarded scalar path
        for (int kc = 0; kc < nSlices; kc++) {
            const int k0 = kc * 16;
            for (int q = tid; q < 1024; q += 256) {
                int rr = q >> 3, p = q & 7;
                int k = k0 + 2 * p;
                float f0 = (k < K)     ? A[(size_t)(rowBase + rr) * lda + k]     : 0.f;
                float f1 = (k + 1 < K) ? A[(size_t)(rowBase + rr) * lda + k + 1] : 0.f;
                uint2 s = split_pair(f0, f1);
                sm[0][0][0][rr][p] = s.x; sm[0][0][1][rr][p] = s.y;
                f0 = (k < K)     ? B[(size_t)(colBase + rr) * ldb + k]     : 0.f;
                f1 = (k + 1 < K) ? B[(size_t)(colBase + rr) * ldb + k + 1] : 0.f;
                s = split_pair(f0, f1);
                sm[0][1][0][rr][p] = s.x; sm[0][1][1][rr][p] = s.y;
            }
            __syncthreads();
            compute(0);
            __syncthreads();
        }
    }

    if (!AQ) {
#pragma unroll
        for (int mt = 0; mt < 2; mt++) {
            int r0 = rowBase + warpM * 32 + mt * 16 + gid;
#pragma unroll
            for (int nt = 0; nt < 8; nt++) {
                int cc = colBase + warpN * 64 + nt * 8 + 2 * tg;
                float b0v = bias ? __ldg(bias + cc) : 0.f;
                float b1v = bias ? __ldg(bias + cc + 1) : 0.f;
                float v0 = acc[mt][nt][0] + b0v, v1 = acc[mt][nt][1] + b1v;
                float v2 = acc[mt][nt][2] + b0v, v3 = acc[mt][nt][3] + b1v;
                if (relu) {
                    v0 = fmaxf(v0, 0.f); v1 = fmaxf(v1, 0.f);
                    v2 = fmaxf(v2, 0.f); v3 = fmaxf(v3, 0.f);
                }
                *(float2*)&C[(size_t)r0 * ldc + cc] = make_float2(v0, v1);
                *(float2*)&C[(size_t)(r0 + 8) * ldc + cc] = make_float2(v2, v3);
            }
        }
    } else {
        float p[2][2] = {{0.f, 0.f}, {0.f, 0.f}};
#pragma unroll
        for (int mt = 0; mt < 2; mt++) {
            int r0 = rowBase + warpM * 32 + mt * 16 + gid;
            const float* h0 = hterm + (size_t)(r0 & (BSZ - 1)) * HDIM;
            const float* h1 = hterm + (size_t)((r0 + 8) & (BSZ - 1)) * HDIM;
#pragma unroll
            for (int nt = 0; nt < 8; nt++) {
                int cc = colBase + warpN * 64 + nt * 8 + 2 * tg;
                float w0 = __ldg(Wa2 + cc), w1 = __ldg(Wa2 + cc + 1);
                p[mt][0] += fmaxf(acc[mt][nt][0] + __ldg(h0 + cc), 0.f) * w0
                          + fmaxf(acc[mt][nt][1] + __ldg(h0 + cc + 1), 0.f) * w1;
                p[mt][1] += fmaxf(acc[mt][nt][2] + __ldg(h1 + cc), 0.f) * w0
                          + fmaxf(acc[mt][nt][3] + __ldg(h1 + cc + 1), 0.f) * w1;
            }
        }
#pragma unroll
        for (int mt = 0; mt < 2; mt++)
#pragma unroll
            for (int j = 0; j < 2; j++) {
                p[mt][j] += __shfl_xor_sync(0xffffffffu, p[mt][j], 1);
                p[mt][j] += __shfl_xor_sync(0xffffffffu, p[mt][j], 2);
            }
        if (tg == 0) {
#pragma unroll
            for (int mt = 0; mt < 2; mt++) {
                int r0 = rowBase + warpM * 32 + mt * 16 + gid;
                atomicAdd(&C[r0], p[mt][0]);
                atomicAdd(&C[r0 + 8], p[mt][1]);
            }
        }
    }
}

// ---------------------------------------------------------------------------
// SIMT SGEMM (small ops): C[M,N] = A[M,K] @ B[K,N] (+bias) (+relu)
// ---------------------------------------------------------------------------
__global__ void sgemm_kernel(const float* __restrict__ A, const float* __restrict__ Bm,
                             const float* __restrict__ bias, float* __restrict__ C,
                             int M, int N, int K, int lda, int ldb, int ldc, int relu)
{
    constexpr int BM = 128, BN = 128, BK = 8, TM = 8, TN = 8;
    __shared__ float As[BK][BM];
    __shared__ float Bs[BK][BN];

    const int tid = threadIdx.x;
    const int tx = tid & 15, ty = tid >> 4;
    const int rowBase = blockIdx.y * BM;
    const int colBase = blockIdx.x * BN;

    float acc[TM][TN];
#pragma unroll
    for (int i = 0; i < TM; i++)
#pragma unroll
        for (int j = 0; j < TN; j++) acc[i][j] = 0.f;

    const int aRow = tid >> 1, aCol = (tid & 1) * 4;
    const int bRow = tid >> 5, bCol = (tid & 31) * 4;

    for (int k0 = 0; k0 < K; k0 += BK) {
#pragma unroll
        for (int i = 0; i < 4; i++) {
            int k = k0 + aCol + i;
            int m = rowBase + aRow;
            As[aCol + i][aRow] = (m < M && k < K) ? __ldg(&A[(size_t)m * lda + k]) : 0.f;
        }
#pragma unroll
        for (int i = 0; i < 4; i++) {
            int k = k0 + bRow;
            int n = colBase + bCol + i;
            Bs[bRow][bCol + i] = (k < K && n < N) ? __ldg(&Bm[(size_t)k * ldb + n]) : 0.f;
        }
        __syncthreads();
#pragma unroll
        for (int kk = 0; kk < BK; kk++) {
            float a[TM], b[TN];
#pragma unroll
            for (int i = 0; i < TM; i++) a[i] = As[kk][ty * TM + i];
#pragma unroll
            for (int j = 0; j < TN; j++) b[j] = Bs[kk][tx * TN + j];
#pragma unroll
            for (int i = 0; i < TM; i++)
#pragma unroll
                for (int j = 0; j < TN; j++) acc[i][j] += a[i] * b[j];
        }
        __syncthreads();
    }

#pragma unroll
    for (int i = 0; i < TM; i++) {
        int r = rowBase + ty * TM + i;
        if (r >= M) continue;
#pragma unroll
        for (int j = 0; j < TN; j++) {
            int c = colBase + tx * TN + j;
            if (c >= N) continue;
            float v = acc[i][j];
            if (bias) v += __ldg(&bias[c]);
            if (relu) v = fmaxf(v, 0.f);
            C[(size_t)r * ldc + c] = v;
        }
    }
}

// ---------------------------------------------------------------------------
// Attention: one warp per batch element (softmax over raw features).
// ---------------------------------------------------------------------------
template <int D, int Nn>
__global__ void attn_kernel(const float* __restrict__ feats,   // [Nn, B, D]
                            const float* __restrict__ qproj,   // [B, D]
                            float* __restrict__ fw)            // [B, D]
{
    constexpr int NC = (D + 31) / 32;
    const int warp = (blockIdx.x * blockDim.x + threadIdx.x) >> 5;
    const int lane = threadIdx.x & 31;
    if (warp >= BSZ) return;
    const int b = warp;

    float qv[NC];
#pragma unroll
    for (int c = 0; c < NC; c++) {
        int d = lane + c * 32;
        qv[c] = (d < D) ? qproj[(size_t)b * D + d] : 0.f;
    }

    const float scale = rsqrtf((float)ADIM);
    float myE = 0.f, m = -1e30f;
    for (int n = 0; n < Nn; n++) {
        const float* f = feats + ((size_t)n * BSZ + b) * D;
        float p = 0.f;
#pragma unroll
        for (int c = 0; c < NC; c++) {
            int d = lane + c * 32;
            if (d < D) p += f[d] * qv[c];
        }
#pragma unroll
        for (int o = 16; o; o >>= 1) p += __shfl_xor_sync(0xffffffffu, p, o);
        p *= scale;
        if (lane == n) myE = p;
        m = fmaxf(m, p);
    }
    float wgt = (lane < Nn) ? expf(myE - m) : 0.f;
    float s = wgt;
#pragma unroll
    for (int o = 16; o; o >>= 1) s += __shfl_xor_sync(0xffffffffu, s, o);
    const float attnW = wgt / s;

    float acc[NC];
#pragma unroll
    for (int c = 0; c < NC; c++) acc[c] = 0.f;
    for (int n = 0; n < Nn; n++) {
        float a = __shfl_sync(0xffffffffu, attnW, n);
        const float* f = feats + ((size_t)n * BSZ + b) * D;
#pragma unroll
        for (int c = 0; c < NC; c++) {
            int d = lane + c * 32;
            if (d < D) acc[c] += a * f[d];
        }
    }
#pragma unroll
    for (int c = 0; c < NC; c++) {
        int d = lane + c * 32;
        if (d < D) fw[(size_t)b * D + d] = acc[c];
    }
}

// GRU gate fusion
__global__ void gru_gate_kernel(const float* __restrict__ gi, const float* __restrict__ gh,
                                const float* __restrict__ hprev, float* __restrict__ hout)
{
    int idx = blockIdx.x * blockDim.x + threadIdx.x;
    if (idx >= BSZ * HDIM) return;
    int b = idx >> 9, k = idx & (HDIM - 1);
    const float* gib = gi + (size_t)b * 3 * HDIM;
    const float* ghb = gh + (size_t)b * 3 * HDIM;
    float ir = gib[k], iz = gib[HDIM + k], in_ = gib[2 * HDIM + k];
    float hr = ghb[k], hz = ghb[HDIM + k], hn  = ghb[2 * HDIM + k];
    float r = 1.f / (1.f + expf(-(ir + hr)));
    float z = 1.f / (1.f + expf(-(iz + hz)));
    float n = tanhf(in_ + r * hn);
    hout[idx] = (1.f - z) * n + z * hprev[idx];
}

// wo_q head
__global__ void woq_kernel(const float* __restrict__ h, const float* __restrict__ Wwo,
                           const float* __restrict__ bwo, float* __restrict__ out)
{
    int idx = blockIdx.x * blockDim.x + threadIdx.x;
    if (idx >= BSZ * NACT) return;
    int b = idx / NACT, j = idx - b * NACT;
    const float* hb = h + (size_t)b * HDIM;
    float s = bwo[j];
#pragma unroll 8
    for (int k = 0; k < HDIM; k++) s += hb[k] * __ldg(&Wwo[k * NACT + j]);
    out[(size_t)b * QOUT + j] = s;
}

// aq finish: out[b, 6+n] = aqpart[n*B + b] + ba2
__global__ void aqfin_kernel(const float* __restrict__ part, const float* __restrict__ ba2,
                             float* __restrict__ out)
{
    int idx = blockIdx.x * blockDim.x + threadIdx.x;
    if (idx >= M_AQ) return;
    int n = idx >> 12, b = idx & (BSZ - 1);
    out[(size_t)b * QOUT + NACT + n] = part[idx] + __ldg(ba2);
}

// cvec[j] = be2 @ Wa1_top[:, j] + ba1[j]
__global__ void cvec_kernel(const float* __restrict__ be2, const float* __restrict__ Wa1,
                            const float* __restrict__ ba1, float* __restrict__ cvec)
{
    int warp = (blockIdx.x * blockDim.x + threadIdx.x) >> 5;
    int lane = threadIdx.x & 31;
    if (warp >= HDIM) return;
    float s = 0.f;
    for (int k = lane; k < HDIM; k += 32) s += be2[k] * Wa1[(size_t)k * HDIM + warp];
#pragma unroll
    for (int o = 16; o; o >>= 1) s += __shfl_xor_sync(0xffffffffu, s, o);
    if (lane == 0) cvec[warp] = s + ba1[warp];
}

// naive transpose: out[j, i] = in[i, j]  for in[R, C]
__global__ void transpose_kernel(const float* __restrict__ in, float* __restrict__ out,
                                 int R, int C)
{
    int idx = blockIdx.x * blockDim.x + threadIdx.x;
    if (idx >= R * C) return;
    int i = idx / C, j = idx - i * C;
    out[(size_t)j * R + i] = in[idx];
}

// ---------------------------------------------------------------------------
// Host launcher
// ---------------------------------------------------------------------------
extern "C" void kernel_launch(void* const* d_in, const int* in_sizes, int n_in,
                              void* d_out, int out_size)
{
    (void)in_sizes; (void)n_in; (void)out_size;
    const float* own_obs = (const float*)d_in[0];
    const float* ally    = (const float*)d_in[1];
    const float* enemy   = (const float*)d_in[2];
    const float* hidden  = (const float*)d_in[3];
    const float* Wq   = (const float*)d_in[4];
    const float* bq   = (const float*)d_in[5];
    const float* Wak  = (const float*)d_in[6];
    const float* Wav  = (const float*)d_in[8];
    const float* bav  = (const float*)d_in[9];
    const float* Wek  = (const float*)d_in[10];
    const float* Wev  = (const float*)d_in[12];
    const float* bev  = (const float*)d_in[13];
    const float* Wov  = (const float*)d_in[14];
    const float* bov  = (const float*)d_in[15];
    const float* w_ih = (const float*)d_in[16];
    const float* w_hh = (const float*)d_in[17];
    const float* b_ih = (const float*)d_in[18];
    const float* b_hh = (const float*)d_in[19];
    const float* Wwo  = (const float*)d_in[20];
    const float* bwo  = (const float*)d_in[21];
    const float* We1  = (const float*)d_in[22];
    const float* be1  = (const float*)d_in[23];
    const float* We2  = (const float*)d_in[24];
    const float* be2  = (const float*)d_in[25];
    const float* Wa1  = (const float*)d_in[26];
    const float* ba1  = (const float*)d_in[27];
    const float* Wa2  = (const float*)d_in[28];
    const float* ba2  = (const float*)d_in[29];

    float* out   = (float*)d_out;
    float* h_out = out + (size_t)BSZ * QOUT;

    float *p_query, *p_qa, *p_qe, *p_afw, *p_efw, *p_tot, *p_gi, *p_gh;
    float *p_hterm, *p_M, *p_Mt, *p_cvec, *p_WakT, *p_WekT, *p_We1T, *p_Wa1botT;
    float *p_relu1, *p_aqpart;
    cudaGetSymbolAddress((void**)&p_query,   g_query);
    cudaGetSymbolAddress((void**)&p_qa,      g_qa);
    cudaGetSymbolAddress((void**)&p_qe,      g_qe);
    cudaGetSymbolAddress((void**)&p_afw,     g_afw);
    cudaGetSymbolAddress((void**)&p_efw,     g_efw);
    cudaGetSymbolAddress((void**)&p_tot,     g_tot);
    cudaGetSymbolAddress((void**)&p_gi,      g_gi);
    cudaGetSymbolAddress((void**)&p_gh,      g_gh);
    cudaGetSymbolAddress((void**)&p_hterm,   g_hterm);
    cudaGetSymbolAddress((void**)&p_M,       g_M);
    cudaGetSymbolAddress((void**)&p_Mt,      g_Mt);
    cudaGetSymbolAddress((void**)&p_cvec,    g_cvec);
    cudaGetSymbolAddress((void**)&p_WakT,    g_WakT);
    cudaGetSymbolAddress((void**)&p_WekT,    g_WekT);
    cudaGetSymbolAddress((void**)&p_We1T,    g_We1T);
    cudaGetSymbolAddress((void**)&p_Wa1botT, g_Wa1botT);
    cudaGetSymbolAddress((void**)&p_relu1,   g_relu1);
    cudaGetSymbolAddress((void**)&p_aqpart,  g_aqpart);

    const int T = 256;

    // --- weight preprocessing ---
    transpose_kernel<<<(64 * 128 + T - 1) / T, T>>>(Wak, p_WakT, 64, 128);
    transpose_kernel<<<(65 * 128 + T - 1) / T, T>>>(Wek, p_WekT, 65, 128);
    transpose_kernel<<<(65 * 512 + T - 1) / T, T>>>(We1, p_We1T, 65, 512);
    transpose_kernel<<<(512 * 512 + T - 1) / T, T>>>(Wa1 + (size_t)HDIM * HDIM, p_Wa1botT, 512, 512);
    // M = We2 @ Wa1_top ; Mt = M^T ; cvec
    sgemm_kernel<<<dim3(4, 4), T>>>(We2, Wa1, nullptr, p_M, 512, 512, 512, 512, 512, 512, 0);
    transpose_kernel<<<(512 * 512 + T - 1) / T, T>>>(p_M, p_Mt, 512, 512);
    cvec_kernel<<<(HDIM * 32 + T - 1) / T, T>>>(be2, Wa1, ba1, p_cvec);

    // --- projections (SIMT, small) ---
    sgemm_kernel<<<dim3(1, 32), T>>>(own_obs, Wq, bq, p_query, BSZ, ADIM, D_OWN, D_OWN, ADIM, ADIM, 0);
    sgemm_kernel<<<dim3(1, 32), T>>>(p_query, p_WakT, nullptr, p_qa, BSZ, D_AL, ADIM, ADIM, D_AL, D_AL, 0);
    sgemm_kernel<<<dim3(1, 32), T>>>(p_query, p_WekT, nullptr, p_qe, BSZ, D_EN, ADIM, ADIM, D_EN, D_EN, 0);
    sgemm_kernel<<<dim3(2, 32), T>>>(own_obs, Wov, bov, p_tot, BSZ, EDIM, D_OWN, D_OWN, EDIM, 3 * EDIM, 0);

    // --- attention ---
    attn_kernel<D_AL, NALLY><<<BSZ / 8, T>>>(ally, p_qa, p_afw);
    attn_kernel<D_EN, NEN><<<BSZ / 8, T>>>(enemy, p_qe, p_efw);
    sgemm_kernel<<<dim3(2, 32), T>>>(p_afw, Wav, bav, p_tot + EDIM, BSZ, EDIM, D_AL, D_AL, EDIM, 3 * EDIM, 0);
    sgemm_kernel<<<dim3(2, 32), T>>>(p_efw, Wev, bev, p_tot + 2 * EDIM, BSZ, EDIM, D_EN, D_EN, EDIM, 3 * EDIM, 0);

    // --- GRU (bf16-split mma.sync; w_ih/w_hh natively [N,K]) ---
    mma_bf16_gemm<0, 0><<<dim3(12, 32), 256>>>(p_tot, w_ih, b_ih, p_gi,
                                               nullptr, nullptr, 3 * EDIM, 3 * EDIM, 3 * EDIM, 3 * HDIM, 0);
    mma_bf16_gemm<0, 0><<<dim3(12, 32), 256>>>(hidden, w_hh, b_hh, p_gh,
                                               nullptr, nullptr, HDIM, HDIM, HDIM, 3 * HDIM, 0);
    gru_gate_kernel<<<(BSZ * HDIM) / T, T>>>(p_gi, p_gh, hidden, h_out);

    // --- heads ---
    woq_kernel<<<(BSZ * NACT + T - 1) / T, T>>>(h_out, Wwo, bwo, out);
    // relu1 = relu(enemy_flat[131072,65] @ We1 + be1)  (K=65 -> guarded scalar loads)
    mma_bf16_gemm<1, 0><<<dim3(4, 1024), 256>>>(enemy, p_We1T, be1, p_relu1,
                                                nullptr, nullptr, D_EN, D_EN, D_EN, HDIM, 1);
    // hterm = h @ Wa1_bot + cvec
    mma_bf16_gemm<0, 0><<<dim3(4, 32), 256>>>(h_out, p_Wa1botT, p_cvec, p_hterm,
                                              nullptr, nullptr, HDIM, HDIM, HDIM, HDIM, 0);
    // aq = relu(relu1 @ M + hterm) @ Wa2 + ba2  (fused epilogue into aqpart)
    cudaMemsetAsync(p_aqpart, 0, (size_t)M_AQ * sizeof(float), 0);
    mma_bf16_gemm<0, 1><<<dim3(4, 1024), 256>>>(p_relu1, p_Mt, nullptr, p_aqpart,
                                                p_hterm, Wa2, HDIM, HDIM, HDIM, 0, 0);
    aqfin_kernel<<<M_AQ / T, T>>>(p_aqpart, ba2, out);
}